// round 14
// baseline (speedup 1.0000x reference)
#include <cuda_runtime.h>
#include <cuda_fp16.h>
#include <cstdint>

#define HD 128
#define BM 128
#define BN 64
#define NT 512

#define ROWB 272               // K/V/Q fp16 row: 128 halves + 8 pad = 272 B
#define KVTILE (64 * ROWB)     // 17408

// smem byte offsets. Q (128x272=34816) persists through the k-loop; the same
// region is reused as the partial-O reduction stage in the epilogue.
#define SM_Q    0
#define SM_K0   34816
#define SM_K1   (SM_K0 + KVTILE)     // 52224
#define SM_V0   (SM_K1 + KVTILE)     // 69632
#define SM_V1   (SM_V0 + KVTILE)     // 87040
#define SM_LROW (SM_V1 + KVTILE)     // 104448, 256 floats
#define SM_TOTAL (SM_LROW + 1024)    // 105472

#define STG_STRIDE 132         // epilogue stage row stride (floats), 132%32=4

#define QSCALE 0.12751744516581796f     // log2(e)/sqrt(128)

#define MAX_ITEMS 4096
__device__ int g_items[MAX_ITEMS];
__device__ int g_counter;

__device__ __forceinline__ uint32_t smem_u32(const void* p) {
    uint32_t a;
    asm("{ .reg .u64 t; cvta.to.shared.u64 t, %1; cvt.u32.u64 %0, t; }" : "=r"(a) : "l"(p));
    return a;
}
__device__ __forceinline__ float ex2f(float x) {
    float r; asm("ex2.approx.f32 %0, %1;" : "=f"(r) : "f"(x)); return r;
}
__device__ __forceinline__ uint32_t f22h(float a, float b) {
    __half2 h = __float22half2_rn(make_float2(a, b));
    return *(uint32_t*)&h;
}
__device__ __forceinline__ void mma_f16(float c[4], const uint32_t a[4], uint32_t b0, uint32_t b1) {
    asm volatile(
        "mma.sync.aligned.m16n8k16.row.col.f32.f16.f16.f32 "
        "{%0,%1,%2,%3}, {%4,%5,%6,%7}, {%8,%9}, {%0,%1,%2,%3};"
        : "+f"(c[0]), "+f"(c[1]), "+f"(c[2]), "+f"(c[3])
        : "r"(a[0]), "r"(a[1]), "r"(a[2]), "r"(a[3]), "r"(b0), "r"(b1));
}
__device__ __forceinline__ void ldsm4(uint32_t& r0, uint32_t& r1, uint32_t& r2, uint32_t& r3, uint32_t addr) {
    asm volatile("ldmatrix.sync.aligned.m8n8.x4.shared.b16 {%0,%1,%2,%3}, [%4];"
                 : "=r"(r0), "=r"(r1), "=r"(r2), "=r"(r3) : "r"(addr));
}
__device__ __forceinline__ void ldsm4t(uint32_t& r0, uint32_t& r1, uint32_t& r2, uint32_t& r3, uint32_t addr) {
    asm volatile("ldmatrix.sync.aligned.m8n8.x4.trans.shared.b16 {%0,%1,%2,%3}, [%4];"
                 : "=r"(r0), "=r"(r1), "=r"(r2), "=r"(r3) : "r"(addr));
}
__device__ __forceinline__ void sts64(uint32_t a, uint32_t x, uint32_t y) {
    asm volatile("st.shared.v2.b32 [%0], {%1,%2};" :: "r"(a), "r"(x), "r"(y) : "memory");
}

// ---- pre-kernel: LPT-sorted work list (descending ntiles), reset counter ----
__global__ void sched_kernel(const int* __restrict__ valid_lens, int B, int qtiles) {
    __shared__ int nt[256];
    int t = threadIdx.x;
    if (t < B) nt[t] = (valid_lens[t] + BN - 1) / BN;
    __syncthreads();
    if (t < B) {
        int mine = nt[t];
        int r = 0;
        for (int j = 0; j < B; j++) {
            int d = nt[j] - mine;
            if (d > 0 || (d == 0 && j < t)) r++;
        }
        for (int qx = 0; qx < qtiles; qx++)
            g_items[r * qtiles + qx] = t * qtiles + qx;
    }
    if (t == 0) g_counter = 0;
}

__global__ __launch_bounds__(NT, 1)
void fmha_f16_kernel(const float* __restrict__ q,
                     const float* __restrict__ k,
                     const float* __restrict__ v,
                     const int*   __restrict__ valid_lens,
                     float* __restrict__ out,
                     int Qlen, int Klen, int qtiles, int nitems)
{
    extern __shared__ float smemf[];
    const uint32_t sb = smem_u32(smemf);
    __shared__ int s_item;

    const int tid  = threadIdx.x;
    const int wid  = tid >> 5;       // 0..15
    const int lane = tid & 31;
    const int rb   = wid >> 1;       // row block 0..7 (16 rows each)
    const int cs   = wid & 1;        // key half (k-split for GEMM2)
    const int gr   = lane >> 2;
    const int gc   = lane & 3;
    const int c4   = lane * 4;       // staging float column

    const uint32_t klo = (uint32_t)(((lane & 7) + ((lane >> 4) << 3)) * ROWB + ((lane >> 3) & 1) * 16);
    const uint32_t vlo = (uint32_t)(((lane & 7) + (((lane >> 3) & 1) << 3)) * ROWB + (lane >> 4) * 16);
    const uint32_t qlo = (uint32_t)((rb * 16 + (lane & 15)) * ROWB + (lane >> 4) * 16);

    for (;;) {
        __syncthreads();     // previous item fully done (smem reuse + s_item)
        if (tid == 0) s_item = atomicAdd(&g_counter, 1);
        __syncthreads();
        const int slot = s_item;
        if (slot >= nitems) break;
        const int item = g_items[slot];
        const int b  = item / qtiles;
        const int q0 = (item - b * qtiles) * BM;

        const float* Qp = q + ((size_t)b * Qlen + q0) * HD;
        const float* Kp = k + (size_t)b * Klen * HD;
        const float* Vp = v + (size_t)b * Klen * HD;
        const int vlen   = valid_lens[b];
        const int ntiles = (vlen + BN - 1) / BN;

        // ---- prologue: Q (scaled) fp16 (persists), K[0], V[0] ----
        #pragma unroll
        for (int i = 0; i < 8; i++) {
            int r = wid + 16 * i;
            float4 f = *(const float4*)(Qp + r * HD + c4);
            sts64(sb + SM_Q + (uint32_t)(r * ROWB + c4 * 2),
                  f22h(f.x * QSCALE, f.y * QSCALE), f22h(f.z * QSCALE, f.w * QSCALE));
        }
        #pragma unroll
        for (int i = 0; i < 4; i++) {
            int r = wid + 16 * i;
            float4 f = *(const float4*)(Kp + r * HD + c4);
            sts64(sb + SM_K0 + (uint32_t)(r * ROWB + c4 * 2), f22h(f.x, f.y), f22h(f.z, f.w));
            float4 g = *(const float4*)(Vp + r * HD + c4);
            sts64(sb + SM_V0 + (uint32_t)(r * ROWB + c4 * 2), f22h(g.x, g.y), f22h(g.z, g.w));
        }
        __syncthreads();

        // partial O over full d=128 (this warp's key half only)
        float o[16][4];
        #pragma unroll
        for (int nt = 0; nt < 16; nt++) { o[nt][0] = o[nt][1] = o[nt][2] = o[nt][3] = 0.f; }
        float l1 = 0.f, l2 = 0.f;

        const uint32_t qbase = sb + SM_Q + qlo;

        for (int kb = 0; kb < ntiles; kb++) {
            const int cur = kb & 1;
            const bool more = (kb + 1 < ntiles);
            const uint32_t kb_cur = cur ? SM_K1 : SM_K0;
            const uint32_t kb_nxt = cur ? SM_K0 : SM_K1;
            const uint32_t vb_cur = cur ? SM_V1 : SM_V0;
            const uint32_t vb_nxt = cur ? SM_V0 : SM_V1;
            const float* Kn = Kp + (size_t)(kb + 1) * BN * HD;
            const float* Vn = Vp + (size_t)(kb + 1) * BN * HD;

            // prefetch next K tile to registers (covered by GEMM1)
            float4 kreg[4];
            if (more) {
                #pragma unroll
                for (int i = 0; i < 4; i++)
                    kreg[i] = *(const float4*)(Kn + (wid + 16 * i) * HD + c4);
            }

            // ---- GEMM1: S[16x32] = Q . K[kb]^T (key cols cs*32..+32),
            //      Q A-fragments reloaded per k-step from persistent Q smem ----
            const uint32_t kbase = sb + kb_cur + (uint32_t)(cs * 32 * ROWB) + klo;
            float s[4][4];
            #pragma unroll
            for (int jn = 0; jn < 4; jn++) { s[jn][0] = s[jn][1] = s[jn][2] = s[jn][3] = 0.f; }
            #pragma unroll
            for (int ks = 0; ks < 8; ks++) {
                uint32_t qa[4];
                ldsm4(qa[0], qa[1], qa[2], qa[3], qbase + (uint32_t)(ks * 32));
                #pragma unroll
                for (int jb = 0; jb < 2; jb++) {
                    uint32_t b0, b1, b2, b3;
                    ldsm4(b0, b1, b2, b3, kbase + (uint32_t)(jb * 16 * ROWB + ks * 32));
                    mma_f16(s[2 * jb    ], qa, b0, b1);
                    mma_f16(s[2 * jb + 1], qa, b2, b3);
                }
            }

            // stage K[kb+1] (kreg dies), then prefetch V[kb+1]
            float4 vreg[4];
            if (more) {
                #pragma unroll
                for (int i = 0; i < 4; i++)
                    sts64(sb + kb_nxt + (uint32_t)((wid + 16 * i) * ROWB + c4 * 2),
                          f22h(kreg[i].x, kreg[i].y), f22h(kreg[i].z, kreg[i].w));
                #pragma unroll
                for (int i = 0; i < 4; i++)
                    vreg[i] = *(const float4*)(Vn + (wid + 16 * i) * HD + c4);
            }

            // ---- softmax: p = ex2(s), mask tail; P stays in registers
            //      (C-fragment == A-fragment layout after half2 packing) ----
            const bool tail = (vlen < (kb + 1) * BN);
            const int colq = kb * BN + cs * 32 + gc * 2;
            uint32_t pa[2][4];
            #pragma unroll
            for (int jn = 0; jn < 4; jn++) {
                float p0 = ex2f(s[jn][0]);
                float p1 = ex2f(s[jn][1]);
                float p2 = ex2f(s[jn][2]);
                float p3 = ex2f(s[jn][3]);
                if (tail) {
                    int c0 = colq + jn * 8;
                    if (c0     >= vlen) { p0 = 0.f; p2 = 0.f; }
                    if (c0 + 1 >= vlen) { p1 = 0.f; p3 = 0.f; }
                }
                l1 += p0 + p1;
                l2 += p2 + p3;
                pa[jn >> 1][(jn & 1) * 2    ] = f22h(p0, p1);
                pa[jn >> 1][(jn & 1) * 2 + 1] = f22h(p2, p3);
            }

            // ---- GEMM2 (warp-local): O += P_cs . V[keys cs*32..+32, all 128 d] ----
            const uint32_t vbase = sb + vb_cur + vlo + (uint32_t)(cs * 32 * ROWB);
            #pragma unroll
            for (int t = 0; t < 2; t++) {
                #pragma unroll
                for (int jb = 0; jb < 8; jb++) {
                    uint32_t w0, w1, w2, w3;
                    ldsm4t(w0, w1, w2, w3, vbase + (uint32_t)(t * 16 * ROWB + jb * 32));
                    mma_f16(o[2 * jb    ], pa[t], w0, w1);
                    mma_f16(o[2 * jb + 1], pa[t], w2, w3);
                }
            }

            // stage V[kb+1] (vreg dies)
            if (more) {
                #pragma unroll
                for (int i = 0; i < 4; i++)
                    sts64(sb + vb_nxt + (uint32_t)((wid + 16 * i) * ROWB + c4 * 2),
                          f22h(vreg[i].x, vreg[i].y), f22h(vreg[i].z, vreg[i].w));
            }

            __syncthreads();   // single barrier: K[kb+1], V[kb+1] staged everywhere
        }

        // ---- epilogue: reduce partial O across cs pairs, normalize, store ----
        l1 += __shfl_xor_sync(0xffffffffu, l1, 1);
        l1 += __shfl_xor_sync(0xffffffffu, l1, 2);
        l2 += __shfl_xor_sync(0xffffffffu, l2, 1);
        l2 += __shfl_xor_sync(0xffffffffu, l2, 2);
        float* lrow = smemf + (SM_LROW >> 2);
        if (gc == 0) {
            lrow[cs * 128 + rb * 16 + gr    ] = l1;
            lrow[cs * 128 + rb * 16 + gr + 8] = l2;
        }
        // cs=1 warps stage partial O into the (now dead) Q region
        float* stg = smemf + rb * (16 * STG_STRIDE);
        if (cs == 1) {
            #pragma unroll
            for (int nt = 0; nt < 16; nt++) {
                *(float2*)(stg + (gr    ) * STG_STRIDE + nt * 8 + gc * 2) =
                    make_float2(o[nt][0], o[nt][1]);
                *(float2*)(stg + (gr + 8) * STG_STRIDE + nt * 8 + gc * 2) =
                    make_float2(o[nt][2], o[nt][3]);
            }
        }
        __syncthreads();
        if (cs == 0) {
            const float inv1 = 1.f / (lrow[rb * 16 + gr    ] + lrow[128 + rb * 16 + gr    ]);
            const float inv2 = 1.f / (lrow[rb * 16 + gr + 8] + lrow[128 + rb * 16 + gr + 8]);
            float* Op = out + ((size_t)b * Qlen + q0 + rb * 16) * HD;
            #pragma unroll
            for (int nt = 0; nt < 16; nt++) {
                float2 a0 = *(float2*)(stg + (gr    ) * STG_STRIDE + nt * 8 + gc * 2);
                float2 a1 = *(float2*)(stg + (gr + 8) * STG_STRIDE + nt * 8 + gc * 2);
                *(float2*)(Op + (gr    ) * HD + nt * 8 + gc * 2) =
                    make_float2((o[nt][0] + a0.x) * inv1, (o[nt][1] + a0.y) * inv1);
                *(float2*)(Op + (gr + 8) * HD + nt * 8 + gc * 2) =
                    make_float2((o[nt][2] + a1.x) * inv2, (o[nt][3] + a1.y) * inv2);
            }
        }
    }
}

extern "C" void kernel_launch(void* const* d_in, const int* in_sizes, int n_in,
                              void* d_out, int out_size)
{
    const float* q  = (const float*)d_in[0];
    const float* k  = (const float*)d_in[1];
    const float* v  = (const float*)d_in[2];
    const int*   vl = (const int*)d_in[3];
    float* out = (float*)d_out;

    const int B    = in_sizes[3];
    const int Qlen = in_sizes[0] / (B * HD);
    const int Klen = in_sizes[1] / (B * HD);
    const int qtiles = Qlen / BM;
    const int nitems = B * qtiles;

    int dev = 0, nsm = 148;
    cudaGetDevice(&dev);
    cudaDeviceGetAttribute(&nsm, cudaDevAttrMultiProcessorCount, dev);
    if (nsm > nitems) nsm = nitems;

    cudaFuncSetAttribute(fmha_f16_kernel,
                         cudaFuncAttributeMaxDynamicSharedMemorySize, SM_TOTAL);

    sched_kernel<<<1, 256>>>(vl, B, qtiles);
    fmha_f16_kernel<<<nsm, NT, SM_TOTAL>>>(q, k, v, vl, out, Qlen, Klen, qtiles, nitems);
}

// round 15
// speedup vs baseline: 1.0345x; 1.0345x over previous
#include <cuda_runtime.h>
#include <cuda_fp16.h>
#include <cstdint>

#define HD 128
#define BM 128
#define BN 64
#define NT 640                 // 512 consumer + 128 producer threads
#define NCONS 512

#define ROWB 272               // K/V/Q fp16 row: 128 halves + 8 pad = 272 B
#define PROWB 144              // P fp16 row: 64 halves + 8 pad = 144 B
#define KVTILE (64 * ROWB)     // 17408

// smem byte offsets (Q persists for the whole item; P does NOT overlap it)
#define SM_Q    0                        // 128 x 272 = 34816
#define SM_P0   34816                    // 128 x 144 = 18432
#define SM_P1   53248
#define SM_LROW 71680                    // 256 floats
#define SM_K0   72704
#define SM_K1   (SM_K0 + KVTILE)
#define SM_V0   (SM_K1 + KVTILE)
#define SM_V1   (SM_V0 + KVTILE)
#define SM_V2   (SM_V1 + KVTILE)
#define SM_TOTAL (SM_V2 + KVTILE)        // 159744

#define QSCALE 0.12751744516581796f      // log2(e)/sqrt(128)

#define MAX_ITEMS 4096
__device__ int g_items[MAX_ITEMS];
__device__ int g_counter;

__device__ __forceinline__ uint32_t smem_u32(const void* p) {
    uint32_t a;
    asm("{ .reg .u64 t; cvta.to.shared.u64 t, %1; cvt.u32.u64 %0, t; }" : "=r"(a) : "l"(p));
    return a;
}
__device__ __forceinline__ float ex2f(float x) {
    float r; asm("ex2.approx.f32 %0, %1;" : "=f"(r) : "f"(x)); return r;
}
__device__ __forceinline__ uint32_t f22h(float a, float b) {
    __half2 h = __float22half2_rn(make_float2(a, b));
    return *(uint32_t*)&h;
}
__device__ __forceinline__ void mma_f16(float c[4], const uint32_t a[4], uint32_t b0, uint32_t b1) {
    asm volatile(
        "mma.sync.aligned.m16n8k16.row.col.f32.f16.f16.f32 "
        "{%0,%1,%2,%3}, {%4,%5,%6,%7}, {%8,%9}, {%0,%1,%2,%3};"
        : "+f"(c[0]), "+f"(c[1]), "+f"(c[2]), "+f"(c[3])
        : "r"(a[0]), "r"(a[1]), "r"(a[2]), "r"(a[3]), "r"(b0), "r"(b1));
}
__device__ __forceinline__ void ldsm4(uint32_t& r0, uint32_t& r1, uint32_t& r2, uint32_t& r3, uint32_t addr) {
    asm volatile("ldmatrix.sync.aligned.m8n8.x4.shared.b16 {%0,%1,%2,%3}, [%4];"
                 : "=r"(r0), "=r"(r1), "=r"(r2), "=r"(r3) : "r"(addr));
}
__device__ __forceinline__ void ldsm4t(uint32_t& r0, uint32_t& r1, uint32_t& r2, uint32_t& r3, uint32_t addr) {
    asm volatile("ldmatrix.sync.aligned.m8n8.x4.trans.shared.b16 {%0,%1,%2,%3}, [%4];"
                 : "=r"(r0), "=r"(r1), "=r"(r2), "=r"(r3) : "r"(addr));
}
__device__ __forceinline__ void sts64(uint32_t a, uint32_t x, uint32_t y) {
    asm volatile("st.shared.v2.b32 [%0], {%1,%2};" :: "r"(a), "r"(x), "r"(y) : "memory");
}
__device__ __forceinline__ void sts32(uint32_t a, uint32_t x) {
    asm volatile("st.shared.b32 [%0], %1;" :: "r"(a), "r"(x) : "memory");
}

// ---- pre-kernel: LPT-sorted work list (descending ntiles), reset counter ----
__global__ void sched_kernel(const int* __restrict__ valid_lens, int B, int qtiles) {
    __shared__ int nt[256];
    int t = threadIdx.x;
    if (t < B) nt[t] = (valid_lens[t] + BN - 1) / BN;
    __syncthreads();
    if (t < B) {
        int mine = nt[t];
        int r = 0;
        for (int j = 0; j < B; j++) {
            int d = nt[j] - mine;
            if (d > 0 || (d == 0 && j < t)) r++;
        }
        for (int qx = 0; qx < qtiles; qx++)
            g_items[r * qtiles + qx] = t * qtiles + qx;
    }
    if (t == 0) g_counter = 0;
}

// producer staging: copy one 64x128 fp32 tile (Kt, Vt) into fp16 smem tiles
__device__ __forceinline__ void stage_kv(const float* __restrict__ Kt,
                                         const float* __restrict__ Vt,
                                         uint32_t kdst, uint32_t vdst, int tid2)
{
    #pragma unroll
    for (int c = 0; c < 4; c++) {
        float4 kr[4], vr[4];
        #pragma unroll
        for (int i = 0; i < 4; i++) {
            int idx = tid2 + 128 * (4 * c + i);
            kr[i] = *(const float4*)(Kt + (idx >> 5) * HD + (idx & 31) * 4);
            vr[i] = *(const float4*)(Vt + (idx >> 5) * HD + (idx & 31) * 4);
        }
        #pragma unroll
        for (int i = 0; i < 4; i++) {
            int idx = tid2 + 128 * (4 * c + i);
            uint32_t off = (uint32_t)((idx >> 5) * ROWB + (idx & 31) * 8);
            sts64(kdst + off, f22h(kr[i].x, kr[i].y), f22h(kr[i].z, kr[i].w));
            sts64(vdst + off, f22h(vr[i].x, vr[i].y), f22h(vr[i].z, vr[i].w));
        }
    }
}

__global__ __launch_bounds__(NT, 1)
void fmha_f16_kernel(const float* __restrict__ q,
                     const float* __restrict__ k,
                     const float* __restrict__ v,
                     const int*   __restrict__ valid_lens,
                     float* __restrict__ out,
                     int Qlen, int Klen, int qtiles, int nitems)
{
    extern __shared__ float smemf[];
    const uint32_t sb = smem_u32(smemf);
    __shared__ int s_item;

    const int tid  = threadIdx.x;
    const int wid  = tid >> 5;       // 0..19
    const int lane = tid & 31;
    const bool cons = (wid < 16);
    const int rb   = wid >> 1;       // consumer: row block 0..7
    const int cs   = wid & 1;        // consumer: column side
    const int gr   = lane >> 2;
    const int gc   = lane & 3;
    const int c4   = lane * 4;
    const int tid2 = tid - NCONS;    // producer: 0..127

    const uint32_t klo = (uint32_t)(((lane & 7) + ((lane >> 4) << 3)) * ROWB + ((lane >> 3) & 1) * 16);
    const uint32_t vlo = (uint32_t)(((lane & 7) + (((lane >> 3) & 1) << 3)) * ROWB + (lane >> 4) * 16);
    const uint32_t plo = (uint32_t)((rb * 16 + (lane & 15)) * PROWB + (lane >> 4) * 16);
    const uint32_t pst = (uint32_t)((rb * 16 + gr) * PROWB + (cs * 32 + gc * 2) * 2);
    const uint32_t qlo = (uint32_t)((rb * 16 + (lane & 15)) * ROWB + (lane >> 4) * 16);

    for (;;) {
        __syncthreads();     // previous item fully done (smem reuse + s_item)
        if (tid == 0) s_item = atomicAdd(&g_counter, 1);
        __syncthreads();
        const int slot = s_item;
        if (slot >= nitems) break;
        const int item = g_items[slot];
        const int b  = item / qtiles;
        const int q0 = (item - b * qtiles) * BM;

        const float* Qp = q + ((size_t)b * Qlen + q0) * HD;
        const float* Kp = k + (size_t)b * Klen * HD;
        const float* Vp = v + (size_t)b * Klen * HD;
        const int vlen   = valid_lens[b];
        const int ntiles = (vlen + BN - 1) / BN;

        // ---- prologue: consumers stage Q (scaled); producers stage K[0], V[0] ----
        if (cons) {
            #pragma unroll
            for (int i = 0; i < 8; i++) {
                int r = wid + 16 * i;
                float4 f = *(const float4*)(Qp + r * HD + c4);
                sts64(sb + SM_Q + (uint32_t)(r * ROWB + c4 * 2),
                      f22h(f.x * QSCALE, f.y * QSCALE), f22h(f.z * QSCALE, f.w * QSCALE));
            }
        } else {
            stage_kv(Kp, Vp, sb + SM_K0, sb + SM_V0, tid2);
        }
        __syncthreads();

        float o[8][4];
        #pragma unroll
        for (int nt = 0; nt < 8; nt++) { o[nt][0] = o[nt][1] = o[nt][2] = o[nt][3] = 0.f; }
        float l1 = 0.f, l2 = 0.f;

        // V triple-buffer rotation (tracked by every thread)
        uint32_t vcur = sb + SM_V0, vnxt = sb + SM_V1, vthr = sb + SM_V2;
        const uint32_t qbase = sb + SM_Q + qlo;

        for (int kb = 0; kb < ntiles; kb++) {
            const int cur = kb & 1;
            const uint32_t pb_cur = cur ? SM_P1 : SM_P0;

            if (cons) {
                // ---- GEMM1: S[16x32] = Q . K[kb]^T (Q A-frags reloaded per k-step) ----
                const uint32_t kbase = sb + (cur ? SM_K1 : SM_K0)
                                     + (uint32_t)(cs * 32 * ROWB) + klo;
                float s[4][4];
                #pragma unroll
                for (int jn = 0; jn < 4; jn++) { s[jn][0] = s[jn][1] = s[jn][2] = s[jn][3] = 0.f; }
                #pragma unroll
                for (int ks = 0; ks < 8; ks++) {
                    uint32_t qa[4];
                    ldsm4(qa[0], qa[1], qa[2], qa[3], qbase + (uint32_t)(ks * 32));
                    #pragma unroll
                    for (int jb = 0; jb < 2; jb++) {
                        uint32_t b0, b1, b2, b3;
                        ldsm4(b0, b1, b2, b3, kbase + (uint32_t)(jb * 16 * ROWB + ks * 32));
                        mma_f16(s[2 * jb    ], qa, b0, b1);
                        mma_f16(s[2 * jb + 1], qa, b2, b3);
                    }
                }

                // ---- softmax: p = ex2(s), mask tail, store P[kb] ----
                const bool tail = (vlen < (kb + 1) * BN);
                const int colq = kb * BN + cs * 32 + gc * 2;
                #pragma unroll
                for (int jn = 0; jn < 4; jn++) {
                    float p0 = ex2f(s[jn][0]);
                    float p1 = ex2f(s[jn][1]);
                    float p2 = ex2f(s[jn][2]);
                    float p3 = ex2f(s[jn][3]);
                    if (tail) {
                        int c0 = colq + jn * 8;
                        if (c0     >= vlen) { p0 = 0.f; p2 = 0.f; }
                        if (c0 + 1 >= vlen) { p1 = 0.f; p3 = 0.f; }
                    }
                    l1 += p0 + p1;
                    l2 += p2 + p3;
                    sts32(sb + pb_cur + pst + (uint32_t)(jn * 16),             f22h(p0, p1));
                    sts32(sb + pb_cur + pst + (uint32_t)(8 * PROWB + jn * 16), f22h(p2, p3));
                }
            } else {
                // ---- producers: stage K[kb+1], V[kb+1] ----
                if (kb + 1 < ntiles) {
                    stage_kv(Kp + (size_t)(kb + 1) * BN * HD,
                             Vp + (size_t)(kb + 1) * BN * HD,
                             sb + (cur ? SM_K0 : SM_K1), vnxt, tid2);
                }
            }

            __syncthreads();    // single barrier: P[kb], K[kb+1], V[kb+1] visible

            if (cons) {
                // ---- GEMM2: O[16x64] += P[kb] . V[kb] (d-cols cs*64..+64) ----
                const uint32_t pabase = sb + pb_cur + plo;
                const uint32_t vbase  = vcur + vlo + (uint32_t)(cs * 128);
                #pragma unroll
                for (int ks2 = 0; ks2 < 4; ks2++) {
                    uint32_t pa[4];
                    ldsm4(pa[0], pa[1], pa[2], pa[3], pabase + (uint32_t)(ks2 * 32));
                    #pragma unroll
                    for (int jb = 0; jb < 4; jb++) {
                        uint32_t w0, w1, w2, w3;
                        ldsm4t(w0, w1, w2, w3, vbase + (uint32_t)(ks2 * 16 * ROWB + jb * 32));
                        mma_f16(o[2 * jb    ], pa, w0, w1);
                        mma_f16(o[2 * jb + 1], pa, w2, w3);
                    }
                }
            }

            // rotate V buffers (all threads)
            { uint32_t t = vcur; vcur = vnxt; vnxt = vthr; vthr = t; }
        }

        // ---- epilogue: combine column-side row sums, normalize, store ----
        float* lrow = smemf + (SM_LROW >> 2);
        if (cons) {
            l1 += __shfl_xor_sync(0xffffffffu, l1, 1);
            l1 += __shfl_xor_sync(0xffffffffu, l1, 2);
            l2 += __shfl_xor_sync(0xffffffffu, l2, 1);
            l2 += __shfl_xor_sync(0xffffffffu, l2, 2);
            if (gc == 0) {
                lrow[cs * 128 + rb * 16 + gr    ] = l1;
                lrow[cs * 128 + rb * 16 + gr + 8] = l2;
            }
        }
        __syncthreads();
        if (cons) {
            const float inv1 = 1.f / (lrow[rb * 16 + gr    ] + lrow[128 + rb * 16 + gr    ]);
            const float inv2 = 1.f / (lrow[rb * 16 + gr + 8] + lrow[128 + rb * 16 + gr + 8]);
            float* Op = out + ((size_t)b * Qlen + q0 + rb * 16) * HD + cs * 64;
            #pragma unroll
            for (int nt = 0; nt < 8; nt++) {
                *(float2*)(Op + (gr    ) * HD + nt * 8 + gc * 2) =
                    make_float2(o[nt][0] * inv1, o[nt][1] * inv1);
                *(float2*)(Op + (gr + 8) * HD + nt * 8 + gc * 2) =
                    make_float2(o[nt][2] * inv2, o[nt][3] * inv2);
            }
        }
    }
}

extern "C" void kernel_launch(void* const* d_in, const int* in_sizes, int n_in,
                              void* d_out, int out_size)
{
    const float* q  = (const float*)d_in[0];
    const float* k  = (const float*)d_in[1];
    const float* v  = (const float*)d_in[2];
    const int*   vl = (const int*)d_in[3];
    float* out = (float*)d_out;

    const int B    = in_sizes[3];
    const int Qlen = in_sizes[0] / (B * HD);
    const int Klen = in_sizes[1] / (B * HD);
    const int qtiles = Qlen / BM;
    const int nitems = B * qtiles;

    int dev = 0, nsm = 148;
    cudaGetDevice(&dev);
    cudaDeviceGetAttribute(&nsm, cudaDevAttrMultiProcessorCount, dev);
    if (nsm > nitems) nsm = nitems;

    cudaFuncSetAttribute(fmha_f16_kernel,
                         cudaFuncAttributeMaxDynamicSharedMemorySize, SM_TOTAL);

    sched_kernel<<<1, 256>>>(vl, B, qtiles);
    fmha_f16_kernel<<<nsm, NT, SM_TOTAL>>>(q, k, v, vl, out, Qlen, Klen, qtiles, nitems);
}

// round 16
// speedup vs baseline: 1.0923x; 1.0559x over previous
#include <cuda_runtime.h>
#include <cuda_fp16.h>
#include <cstdint>

#define HD 128
#define BM 128
#define BN 64
#define NT 512

#define ROWB 272               // K/V/Q fp16 row: 128 halves + 8 pad = 272 B
#define PROWB 144              // P fp16 row: 64 halves + 8 pad = 144 B
#define KVTILE (64 * ROWB)     // 17408

// smem byte offsets; Q prologue (34816 B) overlaps P0+P1 (36864 B)
#define SM_P0   0
#define SM_P1   18432
#define SM_LROW 36864          // 256 floats
#define SM_K0   37888
#define SM_K1   (SM_K0 + KVTILE)
#define SM_V0   (SM_K1 + KVTILE)
#define SM_V1   (SM_V0 + KVTILE)
#define SM_V2   (SM_V1 + KVTILE)
#define SM_TOTAL (SM_V2 + KVTILE)    // 124928
#define SM_Q    0

#define QSCALE 0.12751744516581796f     // log2(e)/sqrt(128)

#define MAX_ITEMS 4096
__device__ int g_items[MAX_ITEMS];
__device__ int g_counter;

__device__ __forceinline__ uint32_t smem_u32(const void* p) {
    uint32_t a;
    asm("{ .reg .u64 t; cvta.to.shared.u64 t, %1; cvt.u32.u64 %0, t; }" : "=r"(a) : "l"(p));
    return a;
}
__device__ __forceinline__ float ex2f(float x) {
    float r; asm("ex2.approx.f32 %0, %1;" : "=f"(r) : "f"(x)); return r;
}
__device__ __forceinline__ uint32_t f22h(float a, float b) {
    __half2 h = __float22half2_rn(make_float2(a, b));
    return *(uint32_t*)&h;
}
__device__ __forceinline__ void mma_f16(float c[4], const uint32_t a[4], uint32_t b0, uint32_t b1) {
    asm volatile(
        "mma.sync.aligned.m16n8k16.row.col.f32.f16.f16.f32 "
        "{%0,%1,%2,%3}, {%4,%5,%6,%7}, {%8,%9}, {%0,%1,%2,%3};"
        : "+f"(c[0]), "+f"(c[1]), "+f"(c[2]), "+f"(c[3])
        : "r"(a[0]), "r"(a[1]), "r"(a[2]), "r"(a[3]), "r"(b0), "r"(b1));
}
__device__ __forceinline__ void ldsm4(uint32_t& r0, uint32_t& r1, uint32_t& r2, uint32_t& r3, uint32_t addr) {
    asm volatile("ldmatrix.sync.aligned.m8n8.x4.shared.b16 {%0,%1,%2,%3}, [%4];"
                 : "=r"(r0), "=r"(r1), "=r"(r2), "=r"(r3) : "r"(addr));
}
__device__ __forceinline__ void ldsm4t(uint32_t& r0, uint32_t& r1, uint32_t& r2, uint32_t& r3, uint32_t addr) {
    asm volatile("ldmatrix.sync.aligned.m8n8.x4.trans.shared.b16 {%0,%1,%2,%3}, [%4];"
                 : "=r"(r0), "=r"(r1), "=r"(r2), "=r"(r3) : "r"(addr));
}
__device__ __forceinline__ void sts64(uint32_t a, uint32_t x, uint32_t y) {
    asm volatile("st.shared.v2.b32 [%0], {%1,%2};" :: "r"(a), "r"(x), "r"(y) : "memory");
}
__device__ __forceinline__ void sts32(uint32_t a, uint32_t x) {
    asm volatile("st.shared.b32 [%0], %1;" :: "r"(a), "r"(x) : "memory");
}

// ---- pre-kernel: LPT-sorted work list (descending ntiles), reset counter ----
__global__ void sched_kernel(const int* __restrict__ valid_lens, int B, int qtiles) {
    __shared__ int nt[256];
    int t = threadIdx.x;
    if (t < B) nt[t] = (valid_lens[t] + BN - 1) / BN;
    __syncthreads();
    if (t < B) {
        int mine = nt[t];
        int r = 0;
        for (int j = 0; j < B; j++) {
            int d = nt[j] - mine;
            if (d > 0 || (d == 0 && j < t)) r++;
        }
        for (int qx = 0; qx < qtiles; qx++)
            g_items[r * qtiles + qx] = t * qtiles + qx;
    }
    if (t == 0) g_counter = 0;
}

// One GEMM2 quarter-step (ks2): P A-frag + 4 V B-frags + 8 MMAs into o
__device__ __forceinline__ void g2_step(float (&o)[8][4], uint32_t pabase, uint32_t vbase, int ks2) {
    uint32_t pa[4];
    ldsm4(pa[0], pa[1], pa[2], pa[3], pabase + (uint32_t)(ks2 * 32));
    #pragma unroll
    for (int jb = 0; jb < 4; jb++) {
        uint32_t w0, w1, w2, w3;
        ldsm4t(w0, w1, w2, w3, vbase + (uint32_t)(ks2 * 16 * ROWB + jb * 32));
        mma_f16(o[2 * jb    ], pa, w0, w1);
        mma_f16(o[2 * jb + 1], pa, w2, w3);
    }
}

__global__ __launch_bounds__(NT, 1)
void fmha_f16_kernel(const float* __restrict__ q,
                     const float* __restrict__ k,
                     const float* __restrict__ v,
                     const int*   __restrict__ valid_lens,
                     float* __restrict__ out,
                     int Qlen, int Klen, int qtiles, int nitems)
{
    extern __shared__ float smemf[];
    const uint32_t sb = smem_u32(smemf);
    __shared__ int s_item;

    const int tid  = threadIdx.x;
    const int wid  = tid >> 5;       // 0..15
    const int lane = tid & 31;
    const int rb   = wid >> 1;       // row block 0..7 (16 rows each)
    const int cs   = wid & 1;        // column side
    const int gr   = lane >> 2;
    const int gc   = lane & 3;
    const int c4   = lane * 4;       // staging float column

    const uint32_t klo = (uint32_t)(((lane & 7) + ((lane >> 4) << 3)) * ROWB + ((lane >> 3) & 1) * 16);
    const uint32_t vlo = (uint32_t)(((lane & 7) + (((lane >> 3) & 1) << 3)) * ROWB + (lane >> 4) * 16);
    const uint32_t plo = (uint32_t)((rb * 16 + (lane & 15)) * PROWB + (lane >> 4) * 16);
    const uint32_t pst = (uint32_t)((rb * 16 + gr) * PROWB + (cs * 32 + gc * 2) * 2);

    for (;;) {
        __syncthreads();     // previous item fully done (smem reuse + s_item)
        if (tid == 0) s_item = atomicAdd(&g_counter, 1);
        __syncthreads();
        const int slot = s_item;
        if (slot >= nitems) break;
        const int item = g_items[slot];
        const int b  = item / qtiles;
        const int q0 = (item - b * qtiles) * BM;

        const float* Qp = q + ((size_t)b * Qlen + q0) * HD;
        const float* Kp = k + (size_t)b * Klen * HD;
        const float* Vp = v + (size_t)b * Klen * HD;
        const int vlen   = valid_lens[b];
        const int ntiles = (vlen + BN - 1) / BN;

        // ---- prologue: Q (scaled) fp16, K[0], V[0] ----
        #pragma unroll
        for (int i = 0; i < 8; i++) {
            int r = wid + 16 * i;
            float4 f = *(const float4*)(Qp + r * HD + c4);
            sts64(sb + SM_Q + (uint32_t)(r * ROWB + c4 * 2),
                  f22h(f.x * QSCALE, f.y * QSCALE), f22h(f.z * QSCALE, f.w * QSCALE));
        }
        #pragma unroll
        for (int i = 0; i < 4; i++) {
            int r = wid + 16 * i;
            float4 f = *(const float4*)(Kp + r * HD + c4);
            sts64(sb + SM_K0 + (uint32_t)(r * ROWB + c4 * 2), f22h(f.x, f.y), f22h(f.z, f.w));
            float4 g = *(const float4*)(Vp + r * HD + c4);
            sts64(sb + SM_V0 + (uint32_t)(r * ROWB + c4 * 2), f22h(g.x, g.y), f22h(g.z, g.w));
        }
        __syncthreads();

        // ---- register-resident Q A-fragments for this warp's 16 rows ----
        uint32_t qa[8][4];
        {
            const uint32_t qbase = sb + SM_Q
                + (uint32_t)((rb * 16 + (lane & 15)) * ROWB + (lane >> 4) * 16);
            #pragma unroll
            for (int ks = 0; ks < 8; ks++)
                ldsm4(qa[ks][0], qa[ks][1], qa[ks][2], qa[ks][3], qbase + (uint32_t)(ks * 32));
        }
        __syncthreads();   // Q region free -> P buffers

        float o[8][4];
        #pragma unroll
        for (int nt = 0; nt < 8; nt++) { o[nt][0] = o[nt][1] = o[nt][2] = o[nt][3] = 0.f; }
        float l1 = 0.f, l2 = 0.f;

        // V triple-buffer rotation; at iteration t: vcur=V[t], vthr=V[t-1]
        uint32_t vcur = sb + SM_V0, vnxt = sb + SM_V1, vthr = sb + SM_V2;

        for (int kb = 0; kb < ntiles; kb++) {
            const int cur = kb & 1;
            const bool more = (kb + 1 < ntiles);
            const uint32_t kb_cur = cur ? SM_K1 : SM_K0;
            const uint32_t kb_nxt = cur ? SM_K0 : SM_K1;
            const uint32_t pb_cur  = cur ? SM_P1 : SM_P0;
            const uint32_t pb_prev = cur ? SM_P0 : SM_P1;
            const float* Kn = Kp + (size_t)(kb + 1) * BN * HD;
            const float* Vn = Vp + (size_t)(kb + 1) * BN * HD;

            // prefetch next K tile to registers (covered by the fused GEMMs)
            float4 kreg[4];
            if (more) {
                #pragma unroll
                for (int i = 0; i < 4; i++)
                    kreg[i] = *(const float4*)(Kn + (wid + 16 * i) * HD + c4);
            }

            // ---- fused block: GEMM1(kb) into s, interleaved with GEMM2(kb-1) into o ----
            const uint32_t kbase = sb + kb_cur + (uint32_t)(cs * 32 * ROWB) + klo;
            float s[4][4];
            #pragma unroll
            for (int jn = 0; jn < 4; jn++) { s[jn][0] = s[jn][1] = s[jn][2] = s[jn][3] = 0.f; }

            if (kb > 0) {
                const uint32_t pabase = sb + pb_prev + plo;
                const uint32_t vbase  = vthr + vlo + (uint32_t)(cs * 128);
                #pragma unroll
                for (int ks = 0; ks < 8; ks++) {
                    #pragma unroll
                    for (int jb = 0; jb < 2; jb++) {
                        uint32_t b0, b1, b2, b3;
                        ldsm4(b0, b1, b2, b3, kbase + (uint32_t)(jb * 16 * ROWB + ks * 32));
                        mma_f16(s[2 * jb    ], qa[ks], b0, b1);
                        mma_f16(s[2 * jb + 1], qa[ks], b2, b3);
                    }
                    if (ks & 1) g2_step(o, pabase, vbase, ks >> 1);
                }
            } else {
                #pragma unroll
                for (int ks = 0; ks < 8; ks++) {
                    #pragma unroll
                    for (int jb = 0; jb < 2; jb++) {
                        uint32_t b0, b1, b2, b3;
                        ldsm4(b0, b1, b2, b3, kbase + (uint32_t)(jb * 16 * ROWB + ks * 32));
                        mma_f16(s[2 * jb    ], qa[ks], b0, b1);
                        mma_f16(s[2 * jb + 1], qa[ks], b2, b3);
                    }
                }
            }

            // stage K[kb+1] (kreg dies), then prefetch V[kb+1] to registers
            float4 vreg[4];
            if (more) {
                #pragma unroll
                for (int i = 0; i < 4; i++)
                    sts64(sb + kb_nxt + (uint32_t)((wid + 16 * i) * ROWB + c4 * 2),
                          f22h(kreg[i].x, kreg[i].y), f22h(kreg[i].z, kreg[i].w));
                #pragma unroll
                for (int i = 0; i < 4; i++)
                    vreg[i] = *(const float4*)(Vn + (wid + 16 * i) * HD + c4);
            }

            // ---- softmax: p = ex2(s), mask tail, store P[kb] ----
            const bool tail = (vlen < (kb + 1) * BN);
            const int colq = kb * BN + cs * 32 + gc * 2;
            #pragma unroll
            for (int jn = 0; jn < 4; jn++) {
                float p0 = ex2f(s[jn][0]);
                float p1 = ex2f(s[jn][1]);
                float p2 = ex2f(s[jn][2]);
                float p3 = ex2f(s[jn][3]);
                if (tail) {
                    int c0 = colq + jn * 8;
                    if (c0     >= vlen) { p0 = 0.f; p2 = 0.f; }
                    if (c0 + 1 >= vlen) { p1 = 0.f; p3 = 0.f; }
                }
                l1 += p0 + p1;
                l2 += p2 + p3;
                sts32(sb + pb_cur + pst + (uint32_t)(jn * 16),             f22h(p0, p1));
                sts32(sb + pb_cur + pst + (uint32_t)(8 * PROWB + jn * 16), f22h(p2, p3));
            }

            // stage V[kb+1] (vreg dies here)
            if (more) {
                #pragma unroll
                for (int i = 0; i < 4; i++)
                    sts64(vnxt + (uint32_t)((wid + 16 * i) * ROWB + c4 * 2),
                          f22h(vreg[i].x, vreg[i].y), f22h(vreg[i].z, vreg[i].w));
            }

            __syncthreads();    // single barrier: P[kb], K[kb+1], V[kb+1] visible

            // rotate V buffers: vthr becomes V[kb] for next iteration's GEMM2
            { uint32_t t = vcur; vcur = vnxt; vnxt = vthr; vthr = t; }
        }

        // ---- final GEMM2(ntiles-1): P[(ntiles-1)&1], V = vthr ----
        {
            const uint32_t pb_last = ((ntiles - 1) & 1) ? SM_P1 : SM_P0;
            const uint32_t pabase = sb + pb_last + plo;
            const uint32_t vbase  = vthr + vlo + (uint32_t)(cs * 128);
            #pragma unroll
            for (int ks2 = 0; ks2 < 4; ks2++)
                g2_step(o, pabase, vbase, ks2);
        }

        // ---- epilogue: combine column-side row sums, normalize, store ----
        l1 += __shfl_xor_sync(0xffffffffu, l1, 1);
        l1 += __shfl_xor_sync(0xffffffffu, l1, 2);
        l2 += __shfl_xor_sync(0xffffffffu, l2, 1);
        l2 += __shfl_xor_sync(0xffffffffu, l2, 2);
        float* lrow = smemf + (SM_LROW >> 2);
        if (gc == 0) {
            lrow[cs * 128 + rb * 16 + gr    ] = l1;
            lrow[cs * 128 + rb * 16 + gr + 8] = l2;
        }
        __syncthreads();
        const float inv1 = 1.f / (lrow[rb * 16 + gr    ] + lrow[128 + rb * 16 + gr    ]);
        const float inv2 = 1.f / (lrow[rb * 16 + gr + 8] + lrow[128 + rb * 16 + gr + 8]);

        float* Op = out + ((size_t)b * Qlen + q0 + rb * 16) * HD + cs * 64;
        #pragma unroll
        for (int nt = 0; nt < 8; nt++) {
            *(float2*)(Op + (gr    ) * HD + nt * 8 + gc * 2) =
                make_float2(o[nt][0] * inv1, o[nt][1] * inv1);
            *(float2*)(Op + (gr + 8) * HD + nt * 8 + gc * 2) =
                make_float2(o[nt][2] * inv2, o[nt][3] * inv2);
        }
    }
}

extern "C" void kernel_launch(void* const* d_in, const int* in_sizes, int n_in,
                              void* d_out, int out_size)
{
    const float* q  = (const float*)d_in[0];
    const float* k  = (const float*)d_in[1];
    const float* v  = (const float*)d_in[2];
    const int*   vl = (const int*)d_in[3];
    float* out = (float*)d_out;

    const int B    = in_sizes[3];
    const int Qlen = in_sizes[0] / (B * HD);
    const int Klen = in_sizes[1] / (B * HD);
    const int qtiles = Qlen / BM;
    const int nitems = B * qtiles;

    int dev = 0, nsm = 148;
    cudaGetDevice(&dev);
    cudaDeviceGetAttribute(&nsm, cudaDevAttrMultiProcessorCount, dev);
    if (nsm > nitems) nsm = nitems;

    cudaFuncSetAttribute(fmha_f16_kernel,
                         cudaFuncAttributeMaxDynamicSharedMemorySize, SM_TOTAL);

    sched_kernel<<<1, 256>>>(vl, B, qtiles);
    fmha_f16_kernel<<<nsm, NT, SM_TOTAL>>>(q, k, v, vl, out, Qlen, Klen, qtiles, nitems);
}

// round 17
// speedup vs baseline: 1.1789x; 1.0793x over previous
#include <cuda_runtime.h>
#include <cuda_fp16.h>
#include <cstdint>

#define HD 128
#define BM 128
#define BN 64
#define NT 512

#define ROWB 272               // K/V/Q fp16 row: 128 halves + 8 pad = 272 B
#define PROWB 144              // P fp16 row: 64 halves + 8 pad = 144 B
#define KVTILE (64 * ROWB)     // 17408

// smem byte offsets; Q prologue (34816 B) overlaps P0+P1 (36864 B)
#define SM_P0   0
#define SM_P1   18432
#define SM_LROW 36864          // 256 floats
#define SM_K0   37888
#define SM_K1   (SM_K0 + KVTILE)
#define SM_V0   (SM_K1 + KVTILE)
#define SM_V1   (SM_V0 + KVTILE)
#define SM_V2   (SM_V1 + KVTILE)
#define SM_TOTAL (SM_V2 + KVTILE)    // 124928
#define SM_Q    0

#define QSCALE 0.12751744516581796f     // log2(e)/sqrt(128)

#define MAX_ITEMS 4096
__device__ int g_items[MAX_ITEMS];
__device__ int g_counter;

__device__ __forceinline__ uint32_t smem_u32(const void* p) {
    uint32_t a;
    asm("{ .reg .u64 t; cvta.to.shared.u64 t, %1; cvt.u32.u64 %0, t; }" : "=r"(a) : "l"(p));
    return a;
}
__device__ __forceinline__ float ex2f(float x) {
    float r; asm("ex2.approx.f32 %0, %1;" : "=f"(r) : "f"(x)); return r;
}
__device__ __forceinline__ uint32_t f22h(float a, float b) {
    __half2 h = __float22half2_rn(make_float2(a, b));
    return *(uint32_t*)&h;
}
__device__ __forceinline__ void mma_f16(float c[4], const uint32_t a[4], uint32_t b0, uint32_t b1) {
    asm volatile(
        "mma.sync.aligned.m16n8k16.row.col.f32.f16.f16.f32 "
        "{%0,%1,%2,%3}, {%4,%5,%6,%7}, {%8,%9}, {%0,%1,%2,%3};"
        : "+f"(c[0]), "+f"(c[1]), "+f"(c[2]), "+f"(c[3])
        : "r"(a[0]), "r"(a[1]), "r"(a[2]), "r"(a[3]), "r"(b0), "r"(b1));
}
__device__ __forceinline__ void ldsm4(uint32_t& r0, uint32_t& r1, uint32_t& r2, uint32_t& r3, uint32_t addr) {
    asm volatile("ldmatrix.sync.aligned.m8n8.x4.shared.b16 {%0,%1,%2,%3}, [%4];"
                 : "=r"(r0), "=r"(r1), "=r"(r2), "=r"(r3) : "r"(addr));
}
__device__ __forceinline__ void ldsm4t(uint32_t& r0, uint32_t& r1, uint32_t& r2, uint32_t& r3, uint32_t addr) {
    asm volatile("ldmatrix.sync.aligned.m8n8.x4.trans.shared.b16 {%0,%1,%2,%3}, [%4];"
                 : "=r"(r0), "=r"(r1), "=r"(r2), "=r"(r3) : "r"(addr));
}
__device__ __forceinline__ void sts64(uint32_t a, uint32_t x, uint32_t y) {
    asm volatile("st.shared.v2.b32 [%0], {%1,%2};" :: "r"(a), "r"(x), "r"(y) : "memory");
}
__device__ __forceinline__ void sts32(uint32_t a, uint32_t x) {
    asm volatile("st.shared.b32 [%0], %1;" :: "r"(a), "r"(x) : "memory");
}

// ---- pre-kernel: LPT-sorted work list (descending ntiles), reset counter ----
__global__ void sched_kernel(const int* __restrict__ valid_lens, int B, int qtiles) {
    __shared__ int nt[256];
    int t = threadIdx.x;
    if (t < B) nt[t] = (valid_lens[t] + BN - 1) / BN;
    __syncthreads();
    if (t < B) {
        int mine = nt[t];
        int r = 0;
        for (int j = 0; j < B; j++) {
            int d = nt[j] - mine;
            if (d > 0 || (d == 0 && j < t)) r++;
        }
        for (int qx = 0; qx < qtiles; qx++)
            g_items[r * qtiles + qx] = t * qtiles + qx;
    }
    if (t == 0) g_counter = 0;
}

__global__ __launch_bounds__(NT, 1)
void fmha_f16_kernel(const float* __restrict__ q,
                     const float* __restrict__ k,
                     const float* __restrict__ v,
                     const int*   __restrict__ valid_lens,
                     float* __restrict__ out,
                     int Qlen, int Klen, int qtiles, int nitems)
{
    extern __shared__ float smemf[];
    const uint32_t sb = smem_u32(smemf);
    __shared__ int s_item;

    const int tid  = threadIdx.x;
    const int wid  = tid >> 5;       // 0..15
    const int lane = tid & 31;
    const int rb   = wid >> 1;       // row block 0..7 (16 rows each)
    const int cs   = wid & 1;        // column side
    const int gr   = lane >> 2;
    const int gc   = lane & 3;
    const int c4   = lane * 4;       // staging float column

    const uint32_t klo = (uint32_t)(((lane & 7) + ((lane >> 4) << 3)) * ROWB + ((lane >> 3) & 1) * 16);
    const uint32_t vlo = (uint32_t)(((lane & 7) + (((lane >> 3) & 1) << 3)) * ROWB + (lane >> 4) * 16);
    const uint32_t plo = (uint32_t)((rb * 16 + (lane & 15)) * PROWB + (lane >> 4) * 16);
    const uint32_t pst = (uint32_t)((rb * 16 + gr) * PROWB + (cs * 32 + gc * 2) * 2);

    for (;;) {
        __syncthreads();     // previous item fully done (smem reuse + s_item)
        if (tid == 0) s_item = atomicAdd(&g_counter, 1);
        __syncthreads();
        const int slot = s_item;
        if (slot >= nitems) break;
        const int item = g_items[slot];
        const int b  = item / qtiles;
        const int q0 = (item - b * qtiles) * BM;

        const float* Qp = q + ((size_t)b * Qlen + q0) * HD;
        const float* Kp = k + (size_t)b * Klen * HD;
        const float* Vp = v + (size_t)b * Klen * HD;
        const int vlen   = valid_lens[b];
        const int ntiles = (vlen + BN - 1) / BN;

        // ---- prologue: Q (scaled) fp16, K[0], V[0] ----
        #pragma unroll
        for (int i = 0; i < 8; i++) {
            int r = wid + 16 * i;
            float4 f = *(const float4*)(Qp + r * HD + c4);
            sts64(sb + SM_Q + (uint32_t)(r * ROWB + c4 * 2),
                  f22h(f.x * QSCALE, f.y * QSCALE), f22h(f.z * QSCALE, f.w * QSCALE));
        }
        #pragma unroll
        for (int i = 0; i < 4; i++) {
            int r = wid + 16 * i;
            float4 f = *(const float4*)(Kp + r * HD + c4);
            sts64(sb + SM_K0 + (uint32_t)(r * ROWB + c4 * 2), f22h(f.x, f.y), f22h(f.z, f.w));
            float4 g = *(const float4*)(Vp + r * HD + c4);
            sts64(sb + SM_V0 + (uint32_t)(r * ROWB + c4 * 2), f22h(g.x, g.y), f22h(g.z, g.w));
        }
        __syncthreads();

        // ---- register-resident Q A-fragments for this warp's 16 rows ----
        uint32_t qa[8][4];
        {
            const uint32_t qbase = sb + SM_Q
                + (uint32_t)((rb * 16 + (lane & 15)) * ROWB + (lane >> 4) * 16);
            #pragma unroll
            for (int ks = 0; ks < 8; ks++)
                ldsm4(qa[ks][0], qa[ks][1], qa[ks][2], qa[ks][3], qbase + (uint32_t)(ks * 32));
        }
        __syncthreads();   // Q region free -> P buffers

        float o[8][4];
        #pragma unroll
        for (int nt = 0; nt < 8; nt++) { o[nt][0] = o[nt][1] = o[nt][2] = o[nt][3] = 0.f; }
        float l1 = 0.f, l2 = 0.f;

        // V triple-buffer rotation
        uint32_t vcur = sb + SM_V0, vnxt = sb + SM_V1, vthr = sb + SM_V2;

        for (int kb = 0; kb < ntiles; kb++) {
            const int cur = kb & 1;
            const bool more = (kb + 1 < ntiles);
            const uint32_t kb_cur = cur ? SM_K1 : SM_K0;
            const uint32_t kb_nxt = cur ? SM_K0 : SM_K1;
            const uint32_t pb_cur = cur ? SM_P1 : SM_P0;
            const float* Kn = Kp + (size_t)(kb + 1) * BN * HD;
            const float* Vn = Vp + (size_t)(kb + 1) * BN * HD;

            // prefetch next K tile to registers (covered by GEMM1)
            float4 kreg[4];
            if (more) {
                #pragma unroll
                for (int i = 0; i < 4; i++)
                    kreg[i] = *(const float4*)(Kn + (wid + 16 * i) * HD + c4);
            }

            // ---- GEMM1 (pipelined): S[16x32] = Q . K[kb]^T (cols cs*32..+32) ----
            const uint32_t kbase = sb + kb_cur + (uint32_t)(cs * 32 * ROWB) + klo;
            float s[4][4];
            #pragma unroll
            for (int jn = 0; jn < 4; jn++) { s[jn][0] = s[jn][1] = s[jn][2] = s[jn][3] = 0.f; }
            {
                uint32_t f0[4], f1[4];   // current ks fragments (jb=0, jb=1)
                ldsm4(f0[0], f0[1], f0[2], f0[3], kbase);
                ldsm4(f1[0], f1[1], f1[2], f1[3], kbase + (uint32_t)(16 * ROWB));
                #pragma unroll
                for (int ks = 0; ks < 8; ks++) {
                    uint32_t n0[4], n1[4];   // next ks fragments
                    if (ks < 7) {
                        ldsm4(n0[0], n0[1], n0[2], n0[3], kbase + (uint32_t)((ks + 1) * 32));
                        ldsm4(n1[0], n1[1], n1[2], n1[3], kbase + (uint32_t)(16 * ROWB + (ks + 1) * 32));
                    }
                    mma_f16(s[0], qa[ks], f0[0], f0[1]);
                    mma_f16(s[1], qa[ks], f0[2], f0[3]);
                    mma_f16(s[2], qa[ks], f1[0], f1[1]);
                    mma_f16(s[3], qa[ks], f1[2], f1[3]);
                    if (ks < 7) {
                        #pragma unroll
                        for (int j = 0; j < 4; j++) { f0[j] = n0[j]; f1[j] = n1[j]; }
                    }
                }
            }

            // stage next K, then prefetch next V
            float4 vreg[4];
            if (more) {
                #pragma unroll
                for (int i = 0; i < 4; i++)
                    sts64(sb + kb_nxt + (uint32_t)((wid + 16 * i) * ROWB + c4 * 2),
                          f22h(kreg[i].x, kreg[i].y), f22h(kreg[i].z, kreg[i].w));
                #pragma unroll
                for (int i = 0; i < 4; i++)
                    vreg[i] = *(const float4*)(Vn + (wid + 16 * i) * HD + c4);
            }

            // ---- softmax: p = ex2(s), mask tail, store P[kb] ----
            const bool tail = (vlen < (kb + 1) * BN);
            const int colq = kb * BN + cs * 32 + gc * 2;
            #pragma unroll
            for (int jn = 0; jn < 4; jn++) {
                float p0 = ex2f(s[jn][0]);
                float p1 = ex2f(s[jn][1]);
                float p2 = ex2f(s[jn][2]);
                float p3 = ex2f(s[jn][3]);
                if (tail) {
                    int c0 = colq + jn * 8;
                    if (c0     >= vlen) { p0 = 0.f; p2 = 0.f; }
                    if (c0 + 1 >= vlen) { p1 = 0.f; p3 = 0.f; }
                }
                l1 += p0 + p1;
                l2 += p2 + p3;
                sts32(sb + pb_cur + pst + (uint32_t)(jn * 16),             f22h(p0, p1));
                sts32(sb + pb_cur + pst + (uint32_t)(8 * PROWB + jn * 16), f22h(p2, p3));
            }

            // stage next V (vreg dies here)
            if (more) {
                #pragma unroll
                for (int i = 0; i < 4; i++)
                    sts64(vnxt + (uint32_t)((wid + 16 * i) * ROWB + c4 * 2),
                          f22h(vreg[i].x, vreg[i].y), f22h(vreg[i].z, vreg[i].w));
            }

            __syncthreads();    // single barrier: P[kb], K[kb+1], V[kb+1] visible

            // ---- GEMM2 (batched loads): O[16x64] += P[kb] . V[kb] ----
            const uint32_t pabase = sb + pb_cur + plo;
            const uint32_t vbase  = vcur + vlo + (uint32_t)(cs * 128);
            #pragma unroll
            for (int ks2 = 0; ks2 < 4; ks2++) {
                uint32_t pa[4];
                uint32_t w[4][4];
                ldsm4(pa[0], pa[1], pa[2], pa[3], pabase + (uint32_t)(ks2 * 32));
                #pragma unroll
                for (int jb = 0; jb < 4; jb++)
                    ldsm4t(w[jb][0], w[jb][1], w[jb][2], w[jb][3],
                           vbase + (uint32_t)(ks2 * 16 * ROWB + jb * 32));
                #pragma unroll
                for (int jb = 0; jb < 4; jb++) {
                    mma_f16(o[2 * jb    ], pa, w[jb][0], w[jb][1]);
                    mma_f16(o[2 * jb + 1], pa, w[jb][2], w[jb][3]);
                }
            }

            // rotate V buffers
            { uint32_t t = vcur; vcur = vnxt; vnxt = vthr; vthr = t; }
        }

        // ---- epilogue: combine column-side row sums, normalize, store ----
        l1 += __shfl_xor_sync(0xffffffffu, l1, 1);
        l1 += __shfl_xor_sync(0xffffffffu, l1, 2);
        l2 += __shfl_xor_sync(0xffffffffu, l2, 1);
        l2 += __shfl_xor_sync(0xffffffffu, l2, 2);
        float* lrow = smemf + (SM_LROW >> 2);
        if (gc == 0) {
            lrow[cs * 128 + rb * 16 + gr    ] = l1;
            lrow[cs * 128 + rb * 16 + gr + 8] = l2;
        }
        __syncthreads();
        const float inv1 = 1.f / (lrow[rb * 16 + gr    ] + lrow[128 + rb * 16 + gr    ]);
        const float inv2 = 1.f / (lrow[rb * 16 + gr + 8] + lrow[128 + rb * 16 + gr + 8]);

        float* Op = out + ((size_t)b * Qlen + q0 + rb * 16) * HD + cs * 64;
        #pragma unroll
        for (int nt = 0; nt < 8; nt++) {
            *(float2*)(Op + (gr    ) * HD + nt * 8 + gc * 2) =
                make_float2(o[nt][0] * inv1, o[nt][1] * inv1);
            *(float2*)(Op + (gr + 8) * HD + nt * 8 + gc * 2) =
                make_float2(o[nt][2] * inv2, o[nt][3] * inv2);
        }
    }
}

extern "C" void kernel_launch(void* const* d_in, const int* in_sizes, int n_in,
                              void* d_out, int out_size)
{
    const float* q  = (const float*)d_in[0];
    const float* k  = (const float*)d_in[1];
    const float* v  = (const float*)d_in[2];
    const int*   vl = (const int*)d_in[3];
    float* out = (float*)d_out;

    const int B    = in_sizes[3];
    const int Qlen = in_sizes[0] / (B * HD);
    const int Klen = in_sizes[1] / (B * HD);
    const int qtiles = Qlen / BM;
    const int nitems = B * qtiles;

    int dev = 0, nsm = 148;
    cudaGetDevice(&dev);
    cudaDeviceGetAttribute(&nsm, cudaDevAttrMultiProcessorCount, dev);
    if (nsm > nitems) nsm = nitems;

    cudaFuncSetAttribute(fmha_f16_kernel,
                         cudaFuncAttributeMaxDynamicSharedMemorySize, SM_TOTAL);

    sched_kernel<<<1, 256>>>(vl, B, qtiles);
    fmha_f16_kernel<<<nsm, NT, SM_TOTAL>>>(q, k, v, vl, out, Qlen, Klen, qtiles, nitems);
}